// round 6
// baseline (speedup 1.0000x reference)
#include <cuda_runtime.h>

#define BT    65536
#define KM    31
#define BLK   128
#define ROWS  256          // rows per block (2 per thread)
#define XSTR  257          // x tile stride (conflict-free)

// smem float offsets
#define W1T 0
#define B1  768
#define W2T 792
#define B2  1368
#define W3T 1392
#define B3  1968
#define W4T 1992
#define B4  2040
#define XS  2048
#define SMEM_FLOATS (XS + 32 * XSTR)   // 10272 floats = 41088 B

typedef unsigned long long ull;

__device__ float g_s[KM * BT];

// ---------------- f32x2 helpers ----------------
__device__ __forceinline__ ull ffma2(ull a, ull b, ull c) {
    ull d; asm("fma.rn.f32x2 %0, %1, %2, %3;" : "=l"(d) : "l"(a), "l"(b), "l"(c)); return d;
}
__device__ __forceinline__ ull fmul2(ull a, ull b) {
    ull d; asm("mul.rn.f32x2 %0, %1, %2;" : "=l"(d) : "l"(a), "l"(b)); return d;
}
__device__ __forceinline__ ull dup2(float a) {
    ull d; asm("mov.b64 %0, {%1, %1};" : "=l"(d) : "f"(a)); return d;
}
__device__ __forceinline__ ull dup_lo(ull v) {
    ull d; asm("{\n\t.reg .b32 l, h;\n\tmov.b64 {l, h}, %1;\n\tmov.b64 %0, {l, l};\n\t}"
               : "=l"(d) : "l"(v)); return d;
}
__device__ __forceinline__ ull dup_hi(ull v) {
    ull d; asm("{\n\t.reg .b32 l, h;\n\tmov.b64 {l, h}, %1;\n\tmov.b64 %0, {h, h};\n\t}"
               : "=l"(d) : "l"(v)); return d;
}
__device__ __forceinline__ void unpack2(ull v, float& lo, float& hi) {
    asm("mov.b64 {%0, %1}, %2;" : "=f"(lo), "=f"(hi) : "l"(v));
}
// packed LeakyReLU(0.2): 0.6*v + 0.4*|v|
__device__ __forceinline__ ull lrelu2(ull v) {
    const ull C06 = 0x3F19999A3F19999AULL;
    const ull C04 = 0x3ECCCCCD3ECCCCCDULL;
    const ull MSK = 0x7FFFFFFF7FFFFFFFULL;
    return ffma2(C04, v & MSK, fmul2(C06, v));
}

// Full-width 24->24 layer for 2 rows. P = PRE-activations (lrelu fused at
// consumption); Q receives pre-activations. Only P and Q live.
__device__ __forceinline__ void layer24f(const ull* __restrict__ P0, const ull* __restrict__ P1,
                                         ull* __restrict__ Q0, ull* __restrict__ Q1,
                                         const float* wt, const float* bias)
{
    const ull* bp = (const ull*)bias;
    #pragma unroll
    for (int p = 0; p < 12; ++p) { Q0[p] = bp[p]; Q1[p] = bp[p]; }
    #pragma unroll
    for (int hp = 0; hp < 12; ++hp) {
        const ull a0 = lrelu2(P0[hp]);        // P dies as it is consumed
        const ull a1 = lrelu2(P1[hp]);
        const ull de0 = dup_lo(a0), dh0 = dup_hi(a0);
        const ull de1 = dup_lo(a1), dh1 = dup_hi(a1);
        const ulonglong2* we = (const ulonglong2*)(wt + (2*hp)     * 24);
        const ulonglong2* wo = (const ulonglong2*)(wt + (2*hp + 1) * 24);
        #pragma unroll
        for (int q = 0; q < 6; ++q) {
            const ulonglong2 a = we[q];
            Q0[2*q]   = ffma2(a.x, de0, Q0[2*q]);
            Q1[2*q]   = ffma2(a.x, de1, Q1[2*q]);
            Q0[2*q+1] = ffma2(a.y, de0, Q0[2*q+1]);
            Q1[2*q+1] = ffma2(a.y, de1, Q1[2*q+1]);
            const ulonglong2 b = wo[q];
            Q0[2*q]   = ffma2(b.x, dh0, Q0[2*q]);
            Q1[2*q]   = ffma2(b.x, dh1, Q1[2*q]);
            Q0[2*q+1] = ffma2(b.y, dh0, Q0[2*q+1]);
            Q1[2*q+1] = ffma2(b.y, dh1, Q1[2*q+1]);
        }
    }
}

// ---------------- main kernel: one (k, 256-row tile) per block ----------------
__global__ __launch_bounds__(BLK, 4)
void maf_main(const float* __restrict__ x,
              const float* __restrict__ W1, const float* __restrict__ b1,
              const float* __restrict__ W2, const float* __restrict__ b2,
              const float* __restrict__ W3, const float* __restrict__ b3,
              const float* __restrict__ W4, const float* __restrict__ b4,
              float* __restrict__ out)
{
    extern __shared__ __align__(16) float sm[];

    const int tid  = threadIdx.x;
    const int k    = blockIdx.y;
    const int base = blockIdx.x * ROWS;

    // ---- stage weights (transposed: output-pairs contiguous) ----
    {
        const float* gW1 = W1 + k * 768;
        for (int i = tid; i < 768; i += BLK) {
            const int h = i >> 5, j = i & 31;
            sm[W1T + j * 24 + h] = gW1[i];
        }
        const float* gW2 = W2 + k * 576;
        for (int i = tid; i < 576; i += BLK)
            sm[W2T + (i % 24) * 24 + (i / 24)] = gW2[i];
        const float* gW3 = W3 + k * 576;
        for (int i = tid; i < 576; i += BLK)
            sm[W3T + (i % 24) * 24 + (i / 24)] = gW3[i];
        const float* gW4 = W4 + k * 48;
        for (int i = tid; i < 48; i += BLK)
            sm[W4T + (i % 24) * 2 + (i / 24)] = gW4[i];
        if (tid < 24) {
            sm[B1 + tid] = b1[k * 24 + tid];
            sm[B2 + tid] = b2[k * 24 + tid];
            sm[B3 + tid] = b3[k * 24 + tid];
        }
        if (tid < 2) sm[B4 + tid] = b4[k * 2 + tid];
    }
    // ---- stage x tile cols 0..k+1, transposed to [j][row], stride 257 ----
    {
        const int jcmax = (k + 1) >> 2;
        for (int it = tid; it < ROWS * 8; it += BLK) {
            const int jc = it & 7;
            if (jc <= jcmax) {
                const int r = it >> 3;
                const float4 v = ((const float4*)x)[(size_t)(base + r) * 8 + jc];
                sm[XS + (4*jc + 0) * XSTR + r] = v.x;
                sm[XS + (4*jc + 1) * XSTR + r] = v.y;
                sm[XS + (4*jc + 2) * XSTR + r] = v.z;
                sm[XS + (4*jc + 3) * XSTR + r] = v.w;
            }
        }
    }
    __syncthreads();

    ull A0[12], A1[12], B0[12], B1r[12];

    // ---- layer 1: (k+1) -> 24, PRE-activations into A ----
    {
        const ull* bp = (const ull*)(sm + B1);
        #pragma unroll
        for (int p = 0; p < 12; ++p) { A0[p] = bp[p]; A1[p] = bp[p]; }
        #pragma unroll 2
        for (int j = 0; j <= k; ++j) {
            const ull d0 = dup2(sm[XS + j * XSTR + tid]);
            const ull d1 = dup2(sm[XS + j * XSTR + tid + 128]);
            const ulonglong2* w = (const ulonglong2*)(sm + W1T + j * 24);
            #pragma unroll
            for (int q = 0; q < 6; ++q) {
                const ulonglong2 wq = w[q];
                A0[2*q]   = ffma2(wq.x, d0, A0[2*q]);
                A1[2*q]   = ffma2(wq.x, d1, A1[2*q]);
                A0[2*q+1] = ffma2(wq.y, d0, A0[2*q+1]);
                A1[2*q+1] = ffma2(wq.y, d1, A1[2*q+1]);
            }
        }
    }

    // ---- layers 2 & 3 (full-width, lrelu fused at consumption) ----
    layer24f(A0, A1, B0, B1r, sm + W2T, sm + B2);
    layer24f(B0, B1r, A0, A1, sm + W3T, sm + B3);

    // ---- layer 4: 24 -> (s, t) ----
    ull st0, st1;
    {
        st0 = *(const ull*)(sm + B4);
        st1 = st0;
        const ull* w4 = (const ull*)(sm + W4T);
        #pragma unroll
        for (int hp = 0; hp < 12; ++hp) {
            const ull a0 = lrelu2(A0[hp]);
            const ull a1 = lrelu2(A1[hp]);
            const ull we = w4[2*hp], wo = w4[2*hp + 1];
            st0 = ffma2(we, dup_lo(a0), st0);
            st1 = ffma2(we, dup_lo(a1), st1);
            st0 = ffma2(wo, dup_hi(a0), st0);
            st1 = ffma2(wo, dup_hi(a1), st1);
        }
    }

    // ---- epilogue: z[:, 30-k] = x[:, k+1]*exp(s)+t ; s -> g_s ----
    {
        float s, t;
        unpack2(st0, s, t);
        const float xk = sm[XS + (k + 1) * XSTR + tid];
        const int gr = base + tid;
        out[(size_t)gr * 32 + (30 - k)] = xk * expf(s) + t;
        g_s[k * BT + gr] = s;
    }
    {
        float s, t;
        unpack2(st1, s, t);
        const float xk = sm[XS + (k + 1) * XSTR + tid + 128];
        const int gr = base + tid + 128;
        out[(size_t)gr * 32 + (30 - k)] = xk * expf(s) + t;
        g_s[k * BT + gr] = s;
    }
}

// ---------------- log_det reduce + dim-0 leaf ----------------
__global__ void reduce_kernel(const float* __restrict__ x,
                              const float* __restrict__ p0,
                              float* __restrict__ out)
{
    const int b = blockIdx.x * 256 + threadIdx.x;
    const float s0 = p0[0];
    float sum = s0;
    #pragma unroll
    for (int kk = 0; kk < KM; ++kk) sum += g_s[kk * BT + b];
    out[(size_t)BT * 32 + b] = sum;                                   // log_det
    out[(size_t)b * 32 + 31] = x[(size_t)b * 32] * expf(s0) + p0[1];  // z col 31
}

extern "C" void kernel_launch(void* const* d_in, const int* in_sizes, int n_in,
                              void* d_out, int out_size)
{
    const float* x  = (const float*)d_in[0];
    const float* p0 = (const float*)d_in[1];
    const float* W1 = (const float*)d_in[2];
    const float* b1 = (const float*)d_in[3];
    const float* W2 = (const float*)d_in[4];
    const float* b2 = (const float*)d_in[5];
    const float* W3 = (const float*)d_in[6];
    const float* b3 = (const float*)d_in[7];
    const float* W4 = (const float*)d_in[8];
    const float* b4 = (const float*)d_in[9];
    float* out = (float*)d_out;

    const int smem_bytes = SMEM_FLOATS * 4;
    cudaFuncSetAttribute(maf_main, cudaFuncAttributeMaxDynamicSharedMemorySize, smem_bytes);

    maf_main<<<dim3(BT / ROWS, KM), BLK, smem_bytes>>>(x, W1, b1, W2, b2, W3, b3, W4, b4, out);
    reduce_kernel<<<BT / 256, 256>>>(x, p0, out);
}

// round 8
// speedup vs baseline: 1.1804x; 1.1804x over previous
#include <cuda_runtime.h>

#define BT   65536       // batch
#define KM   31          // DIM-1 stacked MLPs
#define BLK  128         // threads per main block; 2 rows/thread -> 256 rows/block

typedef unsigned long long ull;

// ---------------- scratch (device globals: allocation-free) ----------------
__device__ float g_xt[32 * BT];   // x transposed: g_xt[j*BT + b]
__device__ float g_s [KM * BT];   // per-k scale logits: g_s[k*BT + b]

// ---------------- f32x2 helpers ----------------
__device__ __forceinline__ ull ffma2(ull a, ull b, ull c) {
    ull d; asm("fma.rn.f32x2 %0, %1, %2, %3;" : "=l"(d) : "l"(a), "l"(b), "l"(c)); return d;
}
__device__ __forceinline__ ull dup2(float a) {
    ull d; asm("mov.b64 %0, {%1, %1};" : "=l"(d) : "f"(a)); return d;
}
__device__ __forceinline__ void unpack2(ull v, float& lo, float& hi) {
    asm("mov.b64 {%0, %1}, %2;" : "=f"(lo), "=f"(hi) : "l"(v));
}
__device__ __forceinline__ float lrelu(float v) { return fmaxf(v, 0.2f * v); }

// ---------------- smem layout (float offsets), all 16B aligned ----------------
#define XS   0            // x slice [j][r]: up to 32*256
#define W1T  8192         // W1 transposed [j=32][h=24]
#define B1   8960         // 24
#define W2T  8984         // W2 transposed [h=24][H=24]
#define B2   9560
#define W3T  9584
#define B3   10160
#define W4T  10184        // W4 transposed [h=24][o=2]  (s,t) pairs
#define B4   10232        // 2
#define SMF  10236

// 24->24 layer on a row-pair: inputs a0/a1 (24 scalars each, registers),
// weights transposed in smem (pairs (H,H+1) contiguous), outputs o0/o1.
__device__ __forceinline__ void layer24(const float* __restrict__ a0,
                                        const float* __restrict__ a1,
                                        const float* wt, const float* bias,
                                        float* __restrict__ o0,
                                        float* __restrict__ o1)
{
    ull acc0[12], acc1[12];
    const ull* bp = (const ull*)bias;
    #pragma unroll
    for (int p = 0; p < 12; ++p) { acc0[p] = bp[p]; acc1[p] = bp[p]; }
    #pragma unroll
    for (int h = 0; h < 24; ++h) {
        const ull pa = dup2(a0[h]);
        const ull pb = dup2(a1[h]);
        const ulonglong2* w = (const ulonglong2*)(wt + h * 24);
        #pragma unroll
        for (int q = 0; q < 6; ++q) {
            const ulonglong2 wq = w[q];
            acc0[2*q]   = ffma2(wq.x, pa, acc0[2*q]);
            acc1[2*q]   = ffma2(wq.x, pb, acc1[2*q]);
            acc0[2*q+1] = ffma2(wq.y, pa, acc0[2*q+1]);
            acc1[2*q+1] = ffma2(wq.y, pb, acc1[2*q+1]);
        }
    }
    #pragma unroll
    for (int p = 0; p < 12; ++p) {
        float lo, hi;
        unpack2(acc0[p], lo, hi); o0[2*p] = lrelu(lo); o0[2*p+1] = lrelu(hi);
        unpack2(acc1[p], lo, hi); o1[2*p] = lrelu(lo); o1[2*p+1] = lrelu(hi);
    }
}

// ---------------- kernel 1: transpose x into g_xt + dim-0 leaf output ----------------
__global__ void pack_x_kernel(const float* __restrict__ x,
                              const float* __restrict__ p0,
                              float* __restrict__ out)
{
    __shared__ float tile[256 * 33];
    const int tid  = threadIdx.x;
    const int base = blockIdx.x * 256;
    for (int idx = tid; idx < 256 * 32; idx += 256)
        tile[(idx >> 5) * 33 + (idx & 31)] = x[(size_t)base * 32 + idx];
    __syncthreads();
    for (int idx = tid; idx < 256 * 32; idx += 256) {
        const int j = idx >> 8, r = idx & 255;
        g_xt[j * BT + base + r] = tile[r * 33 + j];
    }
    // z col 31 = x[:,0]*exp(s0)+t0  (dim-0 LeafParam)
    out[(size_t)(base + tid) * 32 + 31] = tile[tid * 33] * expf(p0[0]) + p0[1];
}

// ---------------- kernel 2: main — one (k, row-tile) per block ----------------
__global__ __launch_bounds__(BLK, 4)
void maf_main(const float* __restrict__ W1, const float* __restrict__ b1,
              const float* __restrict__ W2, const float* __restrict__ b2,
              const float* __restrict__ W3, const float* __restrict__ b3,
              const float* __restrict__ W4, const float* __restrict__ b4,
              float* __restrict__ out)
{
    __shared__ __align__(16) float sm[SMF];

    const int tid  = threadIdx.x;
    const int k    = blockIdx.y;
    const int base = blockIdx.x * 256;

    // ---- stage x slice (cols 0..k+1) and transposed weights ----
    {
        const int nx = (k + 2) * 256;
        for (int idx = tid; idx < nx; idx += BLK)
            sm[XS + idx] = g_xt[(idx >> 8) * BT + base + (idx & 255)];

        const float* gW1 = W1 + k * 768;
        for (int i = tid; i < 768; i += BLK) {
            const int h = i >> 5, j = i & 31;
            sm[W1T + j * 24 + h] = gW1[i];
        }
        const float* gW2 = W2 + k * 576;
        for (int i = tid; i < 576; i += BLK)
            sm[W2T + (i % 24) * 24 + (i / 24)] = gW2[i];
        const float* gW3 = W3 + k * 576;
        for (int i = tid; i < 576; i += BLK)
            sm[W3T + (i % 24) * 24 + (i / 24)] = gW3[i];
        const float* gW4 = W4 + k * 48;
        for (int i = tid; i < 48; i += BLK)
            sm[W4T + (i % 24) * 2 + (i / 24)] = gW4[i];
        if (tid < 24) {
            sm[B1 + tid] = b1[k * 24 + tid];
            sm[B2 + tid] = b2[k * 24 + tid];
            sm[B3 + tid] = b3[k * 24 + tid];
        }
        if (tid < 2) sm[B4 + tid] = b4[k * 2 + tid];
    }
    __syncthreads();

    // this thread's two rows: base+tid and base+tid+128
    float a0[24], a1[24], c0[24], c1[24];

    // ---- layer 1: (k+1) -> 24, inputs from smem x slice ----
    {
        ull acc0[12], acc1[12];
        const ull* bp = (const ull*)(sm + B1);
        #pragma unroll
        for (int p = 0; p < 12; ++p) { acc0[p] = bp[p]; acc1[p] = bp[p]; }
        for (int j = 0; j <= k; ++j) {
            const ull pa = dup2(sm[XS + j * 256 + tid]);
            const ull pb = dup2(sm[XS + j * 256 + tid + 128]);
            const ulonglong2* w = (const ulonglong2*)(sm + W1T + j * 24);
            #pragma unroll
            for (int q = 0; q < 6; ++q) {
                const ulonglong2 wq = w[q];
                acc0[2*q]   = ffma2(wq.x, pa, acc0[2*q]);
                acc1[2*q]   = ffma2(wq.x, pb, acc1[2*q]);
                acc0[2*q+1] = ffma2(wq.y, pa, acc0[2*q+1]);
                acc1[2*q+1] = ffma2(wq.y, pb, acc1[2*q+1]);
            }
        }
        #pragma unroll
        for (int p = 0; p < 12; ++p) {
            float lo, hi;
            unpack2(acc0[p], lo, hi); a0[2*p] = lrelu(lo); a0[2*p+1] = lrelu(hi);
            unpack2(acc1[p], lo, hi); a1[2*p] = lrelu(lo); a1[2*p+1] = lrelu(hi);
        }
    }

    // ---- layers 2 & 3 ----
    layer24(a0, a1, sm + W2T, sm + B2, c0, c1);
    layer24(c0, c1, sm + W3T, sm + B3, a0, a1);

    // ---- layer 4: 24 -> (s, t), natural (s,t) pairs ----
    ull st0 = *(const ull*)(sm + B4);
    ull st1 = st0;
    #pragma unroll
    for (int h = 0; h < 24; ++h) {
        const ull w  = ((const ull*)(sm + W4T))[h];
        st0 = ffma2(w, dup2(a0[h]), st0);
        st1 = ffma2(w, dup2(a1[h]), st1);
    }
    float s0, t0, s1, t1;
    unpack2(st0, s0, t0);
    unpack2(st1, s1, t1);

    // ---- outputs: z[:, 30-k] = x[:, k+1]*exp(s)+t ; s -> scratch ----
    const int r0 = base + tid;
    const int r1 = base + tid + 128;
    const float xk0 = sm[XS + (k + 1) * 256 + tid];
    const float xk1 = sm[XS + (k + 1) * 256 + tid + 128];
    out[(size_t)r0 * 32 + (30 - k)] = xk0 * expf(s0) + t0;
    out[(size_t)r1 * 32 + (30 - k)] = xk1 * expf(s1) + t1;
    g_s[k * BT + r0] = s0;
    g_s[k * BT + r1] = s1;
}

// ---------------- kernel 3: log_det reduce ----------------
__global__ void reduce_kernel(const float* __restrict__ p0, float* __restrict__ out)
{
    const int b = blockIdx.x * 256 + threadIdx.x;
    float sum = p0[0];
    #pragma unroll
    for (int k = 0; k < KM; ++k) sum += g_s[k * BT + b];
    out[(size_t)BT * 32 + b] = sum;   // log_det
}

extern "C" void kernel_launch(void* const* d_in, const int* in_sizes, int n_in,
                              void* d_out, int out_size)
{
    const float* x  = (const float*)d_in[0];
    const float* p0 = (const float*)d_in[1];
    const float* W1 = (const float*)d_in[2];
    const float* b1 = (const float*)d_in[3];
    const float* W2 = (const float*)d_in[4];
    const float* b2 = (const float*)d_in[5];
    const float* W3 = (const float*)d_in[6];
    const float* b3 = (const float*)d_in[7];
    const float* W4 = (const float*)d_in[8];
    const float* b4 = (const float*)d_in[9];
    float* out = (float*)d_out;

    pack_x_kernel<<<BT / 256, 256>>>(x, p0, out);
    maf_main<<<dim3(BT / 256, KM), BLK>>>(W1, b1, W2, b2, W3, b3, W4, b4, out);
    reduce_kernel<<<BT / 256, 256>>>(p0, out);
}